// round 2
// baseline (speedup 1.0000x reference)
#include <cuda_runtime.h>

#define Bn 32
#define DEn 256
#define Tn 32
#define Cn 128
#define HWn 16384
#define NT 128
#define NTILES (HWn / NT)

// scratch for the dense projection, in both layouts
__device__ float g_et[Bn * Tn * Cn];  // [b][t][c]
__device__ float g_ec[Bn * Cn * Tn];  // [b][c][t]

union F2U { float2 f; unsigned long long u; };

__device__ __forceinline__ float2 ffma2(float2 a, float2 b, float2 c) {
    F2U A, Bu, Cu;
    A.f = a; Bu.f = b; Cu.f = c;
    asm("fma.rn.f32x2 %0, %1, %2, %0;" : "+l"(Cu.u) : "l"(A.u), "l"(Bu.u));
    return Cu.f;
}

// ---------------------------------------------------------------------------
// Kernel A: e_[b][c][t] = sum_d e[b][d][t] * Wd[d][c] + bias[c]
// one block per batch, 256 threads; trivially small (67 MFLOP total)
// ---------------------------------------------------------------------------
__global__ __launch_bounds__(256) void ker_e(const float* __restrict__ e,
                                             const float* __restrict__ Wd,
                                             const float* __restrict__ bias) {
    __shared__ float es[DEn * Tn];  // 32 KB, [d][t]
    int b = blockIdx.x, tid = threadIdx.x;
    const float* eb = e + (size_t)b * DEn * Tn;
    for (int i = tid; i < DEn * Tn; i += 256) es[i] = eb[i];
    __syncthreads();

    int c = tid & 127;
    int t0 = (tid >> 7) * 16;
    float bv = bias[c];
    float acc[16];
#pragma unroll
    for (int i = 0; i < 16; i++) acc[i] = bv;

    for (int d = 0; d < DEn; d++) {
        float w = Wd[d * Cn + c];
#pragma unroll
        for (int i = 0; i < 16; i++) acc[i] = fmaf(w, es[d * Tn + t0 + i], acc[i]);
    }

    float* etb = g_et + b * Tn * Cn;
    float* ecb = g_ec + b * Cn * Tn;
#pragma unroll
    for (int i = 0; i < 16; i++) {
        etb[(t0 + i) * Cn + c] = acc[i];
        ecb[c * Tn + t0 + i] = acc[i];
    }
}

// ---------------------------------------------------------------------------
// Kernel B: per (batch, tile of 128 spatial positions):
//   s[t][n] = sum_c et[t][c] * h[n][c]       (32x128, K=128)
//   beta    = softmax_t(s)
//   out[n][c]      = sum_t ec[c][t] * beta[n][t]   (128x128, K=32)
//   out[n][128+c]  = h[n][c]
// Dynamic smem layout (floats):
//   et  @ 0     : [32][128]            4096
//   ec  @ 4096  : [128][34] padded     4352
//   hs  @ 8448  : [128][130] padded   16640  (stride 130: word-stride = 2 mod 32 -> LDS.64 conflict-free)
//   ss  @ 25088 : [32][128]            4096
//   bt  @ 29184 : [128][34] padded     4352
// total 33536 floats = 134144 bytes
// ---------------------------------------------------------------------------
__global__ __launch_bounds__(256) void ker_attn(const float* __restrict__ h,
                                                float* __restrict__ out) {
    extern __shared__ float smem[];
    float* et = smem;          // [t][c], stride 128
    float* ec = smem + 4096;   // [c][t], stride 34
    float* hs = smem + 8448;   // [n][c], stride 130
    float* ss = smem + 25088;  // [t][n], stride 128
    float* bt = smem + 29184;  // [n][t], stride 34

    int tid = threadIdx.x;
    int tile = blockIdx.x, b = blockIdx.y;

    // ---- phase 0: stage operands ----
    const float* etg = g_et + b * (Tn * Cn);
    const float* ecg = g_ec + b * (Cn * Tn);
    for (int i = tid; i < Tn * Cn; i += 256) {
        et[i] = etg[i];
        int c = i >> 5, t = i & 31;
        ec[c * 34 + t] = ecg[i];
    }
    const float2* hg2 =
        (const float2*)(h + ((size_t)b * HWn + (size_t)tile * NT) * Cn);
    float2* hs2 = (float2*)hs;
    for (int i = tid; i < NT * 64; i += 256) {
        int n = i >> 6, c2 = i & 63;
        hs2[n * 65 + c2] = hg2[n * 64 + c2];
    }
    __syncthreads();

    // ---- phase 1: s GEMM (4t x 4n register tile per thread, f32x2 over c) ----
    {
        const float2* et2 = (const float2*)et;
        int nq = tid & 31;          // lane -> n base (interleaved by 32)
        int t0 = (tid >> 5) * 4;    // warp -> 4 consecutive t
        float2 acc[4][4];
#pragma unroll
        for (int i = 0; i < 4; i++)
#pragma unroll
            for (int j = 0; j < 4; j++) acc[i][j] = make_float2(0.f, 0.f);

#pragma unroll 4
        for (int c2 = 0; c2 < 64; c2++) {
            float2 ev[4], hv[4];
#pragma unroll
            for (int i = 0; i < 4; i++) ev[i] = et2[(t0 + i) * 64 + c2];   // broadcast
#pragma unroll
            for (int j = 0; j < 4; j++) hv[j] = hs2[(nq + 32 * j) * 65 + c2];
#pragma unroll
            for (int i = 0; i < 4; i++)
#pragma unroll
                for (int j = 0; j < 4; j++) acc[i][j] = ffma2(ev[i], hv[j], acc[i][j]);
        }
#pragma unroll
        for (int i = 0; i < 4; i++)
#pragma unroll
            for (int j = 0; j < 4; j++)
                ss[(t0 + i) * 128 + nq + 32 * j] = acc[i][j].x + acc[i][j].y;
    }
    __syncthreads();

    // ---- phase 2: softmax over t, one thread per n ----
    if (tid < 128) {
        int n = tid;
        float m = -1e30f;
#pragma unroll
        for (int t = 0; t < Tn; t++) m = fmaxf(m, ss[t * 128 + n]);
        float sum = 0.f;
#pragma unroll
        for (int t = 0; t < Tn; t++) {
            float ev = __expf(ss[t * 128 + n] - m);
            bt[n * 34 + t] = ev;
            sum += ev;
        }
        float r = __fdividef(1.0f, sum);
#pragma unroll
        for (int t = 0; t < Tn; t++) bt[n * 34 + t] *= r;
    }
    __syncthreads();

    // ---- phase 3: context GEMM (4c x 8n per thread, f32x2 over t) + write c ----
    {
        const float2* ec2 = (const float2*)ec;   // row stride 17 float2
        const float2* bt2 = (const float2*)bt;   // row stride 17 float2
        int nh = tid & 15;
        int cq = tid >> 4;  // 0..15
        size_t outrow0 = (size_t)b * HWn + (size_t)tile * NT;

#pragma unroll
        for (int pass = 0; pass < 2; pass++) {
            int cbase = pass * 64 + cq * 4;
            float2 acc[4][8];
#pragma unroll
            for (int i = 0; i < 4; i++)
#pragma unroll
                for (int j = 0; j < 8; j++) acc[i][j] = make_float2(0.f, 0.f);

#pragma unroll 4
            for (int t2 = 0; t2 < 16; t2++) {
                float2 ev[4], bv[8];
#pragma unroll
                for (int i = 0; i < 4; i++) ev[i] = ec2[(cbase + i) * 17 + t2];  // broadcast
#pragma unroll
                for (int j = 0; j < 8; j++) bv[j] = bt2[(nh + 16 * j) * 17 + t2];
#pragma unroll
                for (int i = 0; i < 4; i++)
#pragma unroll
                    for (int j = 0; j < 8; j++) acc[i][j] = ffma2(ev[i], bv[j], acc[i][j]);
            }
#pragma unroll
            for (int j = 0; j < 8; j++) {
                int n = nh + 16 * j;
                float4 v;
                v.x = acc[0][j].x + acc[0][j].y;
                v.y = acc[1][j].x + acc[1][j].y;
                v.z = acc[2][j].x + acc[2][j].y;
                v.w = acc[3][j].x + acc[3][j].y;
                *(float4*)(out + (outrow0 + n) * 256 + cbase) = v;
            }
        }
    }

    // ---- phase 4: copy h tile to out[..][128:256] (hs stable since phase 0) ----
    {
        const float2* hsr = (const float2*)hs;
        float2* out2 = (float2*)out;
        size_t base2 =
            ((((size_t)b * HWn + (size_t)tile * NT) * 256) + 128) >> 1;
        for (int i = tid; i < NT * 64; i += 256) {
            int n = i >> 6, c2 = i & 63;
            out2[base2 + (size_t)n * 128 + c2] = hsr[n * 65 + c2];
        }
    }
}

// ---------------------------------------------------------------------------
extern "C" void kernel_launch(void* const* d_in, const int* in_sizes, int n_in,
                              void* d_out, int out_size) {
    const float* e    = (const float*)d_in[0];  // [B, DE, T]
    const float* h    = (const float*)d_in[1];  // [B, H, W, C]
    const float* Wd   = (const float*)d_in[2];  // [DE, C]
    const float* bias = (const float*)d_in[3];  // [C]
    float* out = (float*)d_out;                 // [B, H, W, 2C]

    (void)in_sizes; (void)n_in; (void)out_size;

    cudaFuncSetAttribute(ker_attn, cudaFuncAttributeMaxDynamicSharedMemorySize,
                         134144);

    ker_e<<<Bn, 256>>>(e, Wd, bias);
    ker_attn<<<dim3(NTILES, Bn), 256, 134144>>>(h, out);
}

// round 3
// speedup vs baseline: 1.3203x; 1.3203x over previous
#include <cuda_runtime.h>

#define Bn 32
#define DEn 256
#define Tn 32
#define Cn 128
#define HWn 16384
#define NT 128
#define NTILES (HWn / NT)

// scratch for the dense projection, in both layouts
__device__ float g_et[Bn * Tn * Cn];  // [b][t][c]
__device__ float g_ec[Bn * Cn * Tn];  // [b][c][t]

union F2U { float2 f; unsigned long long u; };

__device__ __forceinline__ float2 ffma2(float2 a, float2 b, float2 c) {
    F2U A, Bu, Cu;
    A.f = a; Bu.f = b; Cu.f = c;
    asm("fma.rn.f32x2 %0, %1, %2, %0;" : "+l"(Cu.u) : "l"(A.u), "l"(Bu.u));
    return Cu.f;
}

// ---------------------------------------------------------------------------
// Kernel A: e_[b][c][t] = sum_d e[b][d][t] * Wd[d][c] + bias[c]
// grid (8 t-groups, B), 512 threads: thread = (c, t within group of 4)
// ---------------------------------------------------------------------------
__global__ __launch_bounds__(512) void ker_e(const float* __restrict__ e,
                                             const float* __restrict__ Wd,
                                             const float* __restrict__ bias) {
    __shared__ float es[DEn * 4];  // [d][4t] slice
    int tg = blockIdx.x, b = blockIdx.y;
    int tid = threadIdx.x;
    int c = tid & 127, ti = tid >> 7;  // ti in 0..3
    int t = tg * 4 + ti;

    const float* eb = e + (size_t)b * DEn * Tn;
    for (int i = tid; i < DEn * 4; i += 512) {
        int d = i >> 2, tt = i & 3;
        es[i] = eb[d * Tn + tg * 4 + tt];
    }
    __syncthreads();

    float a0 = bias[c], a1 = 0.f, a2 = 0.f, a3 = 0.f;
#pragma unroll 8
    for (int d = 0; d < DEn; d += 4) {
        a0 = fmaf(Wd[(d + 0) * Cn + c], es[(d + 0) * 4 + ti], a0);
        a1 = fmaf(Wd[(d + 1) * Cn + c], es[(d + 1) * 4 + ti], a1);
        a2 = fmaf(Wd[(d + 2) * Cn + c], es[(d + 2) * 4 + ti], a2);
        a3 = fmaf(Wd[(d + 3) * Cn + c], es[(d + 3) * 4 + ti], a3);
    }
    float a = (a0 + a1) + (a2 + a3);
    g_et[b * Tn * Cn + t * Cn + c] = a;
    g_ec[b * Cn * Tn + c * Tn + t] = a;
}

// ---------------------------------------------------------------------------
// Kernel B, per (batch, 128-spatial tile).
// Dynamic smem (floats), total 25344 floats = 101376 B -> 2 CTAs/SM:
//   et @ 0     : [32][128]                4096
//   ec @ 4096  : [128][34]                4352
//   hs @ 8448  : [128][66]  (c half)      8448   (f2 stride 33 -> conflict-free)
//   ss @ 16896 : [32][128]                4096
//   bt @ 20992 : [128][34]                4352
// ---------------------------------------------------------------------------
__global__ __launch_bounds__(256, 2) void ker_attn(const float* __restrict__ h,
                                                   float* __restrict__ out) {
    extern __shared__ float smem[];
    float* et = smem;          // [t][c], stride 128
    float* ec = smem + 4096;   // [c][t], stride 34
    float* hs = smem + 8448;   // [n][c-half], f2 stride 33
    float* ss = smem + 16896;  // [t][n], stride 128
    float* bt = smem + 20992;  // [n][t], stride 34

    int tid = threadIdx.x;
    int tile = blockIdx.x, b = blockIdx.y;
    size_t row0 = (size_t)b * HWn + (size_t)tile * NT;

    const float2* hg2 = (const float2*)(h + row0 * Cn);
    float2* hs2 = (float2*)hs;

    // ---- phase 0: stage e_ (both layouts) + h chunk 0 ----
    const float* etg = g_et + b * (Tn * Cn);
    const float* ecg = g_ec + b * (Cn * Tn);
    for (int i = tid; i < Tn * Cn; i += 256) {
        et[i] = etg[i];
        ec[(i >> 5) * 34 + (i & 31)] = ecg[i];
    }
    for (int i = tid; i < NT * 32; i += 256) {
        int n = i >> 5, c2 = i & 31;
        hs2[n * 33 + c2] = hg2[n * 64 + c2];
    }
    __syncthreads();

    // ---- phase 1: s GEMM, 2 rounds over c halves, acc persists in regs ----
    const float2* et2 = (const float2*)et;
    int nq = tid & 31;
    int t0 = (tid >> 5) * 4;
    float2 acc[4][4];
#pragma unroll
    for (int i = 0; i < 4; i++)
#pragma unroll
        for (int j = 0; j < 4; j++) acc[i][j] = make_float2(0.f, 0.f);

#pragma unroll
    for (int r = 0; r < 2; r++) {
        if (r) {
            __syncthreads();  // round-0 reads done
            for (int i = tid; i < NT * 32; i += 256) {
                int n = i >> 5, c2 = i & 31;
                hs2[n * 33 + c2] = hg2[n * 64 + 32 + c2];
            }
            __syncthreads();
        }
#pragma unroll 4
        for (int c2 = 0; c2 < 32; c2++) {
            int rc = r * 32 + c2;
            float2 ev[4], hv[4];
#pragma unroll
            for (int i = 0; i < 4; i++) ev[i] = et2[(t0 + i) * 64 + rc];
#pragma unroll
            for (int j = 0; j < 4; j++) hv[j] = hs2[(nq + 32 * j) * 33 + c2];
#pragma unroll
            for (int i = 0; i < 4; i++)
#pragma unroll
                for (int j = 0; j < 4; j++) acc[i][j] = ffma2(ev[i], hv[j], acc[i][j]);
        }
    }
#pragma unroll
    for (int i = 0; i < 4; i++)
#pragma unroll
        for (int j = 0; j < 4; j++)
            ss[(t0 + i) * 128 + nq + 32 * j] = acc[i][j].x + acc[i][j].y;
    __syncthreads();

    // ---- phase 2: softmax (threads 0-127) | h copy, rows 0-63 (threads 128-255)
    const float4* hg4 = (const float4*)(h + row0 * Cn);
    float4* out4 = (float4*)out;
    if (tid < 128) {
        int n = tid;
        float m = -1e30f;
#pragma unroll
        for (int t = 0; t < Tn; t++) m = fmaxf(m, ss[t * 128 + n]);
        float sum = 0.f;
#pragma unroll
        for (int t = 0; t < Tn; t++) {
            float ev = __expf(ss[t * 128 + n] - m);
            bt[n * 34 + t] = ev;
            sum += ev;
        }
        float r = __fdividef(1.0f, sum);
#pragma unroll
        for (int t = 0; t < Tn; t++) bt[n * 34 + t] *= r;
    } else {
        int k = tid - 128;
#pragma unroll
        for (int it = 0; it < 16; it++) {
            int i = it * 128 + k;  // 0..2047 -> n 0..63
            int n = i >> 5, q = i & 31;
            out4[(row0 + n) * 64 + 32 + q] = hg4[n * 32 + q];
        }
    }
    __syncthreads();

    // ---- phase 3: context GEMM (4c x 8n per thread, f32x2 over t) ----
    {
        const float2* ec2 = (const float2*)ec;  // row stride 17 f2
        const float2* bt2 = (const float2*)bt;  // row stride 17 f2
        int nh = tid & 15;
        int cq = tid >> 4;  // 0..15

#pragma unroll
        for (int pass = 0; pass < 2; pass++) {
            int cbase = pass * 64 + cq * 4;
            float2 a3[4][8];
#pragma unroll
            for (int i = 0; i < 4; i++)
#pragma unroll
                for (int j = 0; j < 8; j++) a3[i][j] = make_float2(0.f, 0.f);

#pragma unroll 4
            for (int t2 = 0; t2 < 16; t2++) {
                float2 ev[4], bv[8];
#pragma unroll
                for (int i = 0; i < 4; i++) ev[i] = ec2[(cbase + i) * 17 + t2];
#pragma unroll
                for (int j = 0; j < 8; j++) bv[j] = bt2[(nh + 16 * j) * 17 + t2];
#pragma unroll
                for (int i = 0; i < 4; i++)
#pragma unroll
                    for (int j = 0; j < 8; j++) a3[i][j] = ffma2(ev[i], bv[j], a3[i][j]);
            }
#pragma unroll
            for (int j = 0; j < 8; j++) {
                int n = nh + 16 * j;
                float4 v;
                v.x = a3[0][j].x + a3[0][j].y;
                v.y = a3[1][j].x + a3[1][j].y;
                v.z = a3[2][j].x + a3[2][j].y;
                v.w = a3[3][j].x + a3[3][j].y;
                *(float4*)(out + (row0 + n) * 256 + cbase) = v;
            }
        }
    }

    // ---- phase 4: h copy, rows 64-127 (all threads, gmem->gmem, L2-hot) ----
#pragma unroll
    for (int it = 0; it < 8; it++) {
        int i = 2048 + it * 256 + tid;  // n 64..127
        int n = i >> 5, q = i & 31;
        out4[(row0 + n) * 64 + 32 + q] = hg4[n * 32 + q];
    }
}

// ---------------------------------------------------------------------------
extern "C" void kernel_launch(void* const* d_in, const int* in_sizes, int n_in,
                              void* d_out, int out_size) {
    const float* e    = (const float*)d_in[0];  // [B, DE, T]
    const float* h    = (const float*)d_in[1];  // [B, H, W, C]
    const float* Wd   = (const float*)d_in[2];  // [DE, C]
    const float* bias = (const float*)d_in[3];  // [C]
    float* out = (float*)d_out;                 // [B, H, W, 2C]

    (void)in_sizes; (void)n_in; (void)out_size;

    cudaFuncSetAttribute(ker_attn, cudaFuncAttributeMaxDynamicSharedMemorySize,
                         101376);

    ker_e<<<dim3(8, Bn), 512>>>(e, Wd, bias);
    ker_attn<<<dim3(NTILES, Bn), 256, 101376>>>(h, out);
}

// round 4
// speedup vs baseline: 1.4088x; 1.0671x over previous
#include <cuda_runtime.h>

#define Bn 32
#define DEn 256
#define Tn 32
#define Cn 128
#define HWn 16384
#define NT 128
#define NTILES (HWn / NT)

__device__ float g_et[Bn * Tn * Cn];  // [b][t][c]
__device__ float g_ec[Bn * Cn * Tn];  // [b][c][t]

union F2U { float2 f; unsigned long long u; };

__device__ __forceinline__ float2 ffma2(float2 a, float2 b, float2 c) {
    F2U A, Bu, Cu;
    A.f = a; Bu.f = b; Cu.f = c;
    asm("fma.rn.f32x2 %0, %1, %2, %0;" : "+l"(Cu.u) : "l"(A.u), "l"(Bu.u));
    return Cu.f;
}

// ---------------------------------------------------------------------------
// Kernel A: e_[b][c][t] = sum_d e[b][d][t] * Wd[d][c] + bias[c]
// ---------------------------------------------------------------------------
__global__ __launch_bounds__(512) void ker_e(const float* __restrict__ e,
                                             const float* __restrict__ Wd,
                                             const float* __restrict__ bias) {
    __shared__ float es[DEn * 4];
    int tg = blockIdx.x, b = blockIdx.y;
    int tid = threadIdx.x;
    int c = tid & 127, ti = tid >> 7;
    int t = tg * 4 + ti;

    const float* eb = e + (size_t)b * DEn * Tn;
    for (int i = tid; i < DEn * 4; i += 512) {
        int d = i >> 2, tt = i & 3;
        es[i] = eb[d * Tn + tg * 4 + tt];
    }
    __syncthreads();

    float a0 = bias[c], a1 = 0.f, a2 = 0.f, a3 = 0.f;
#pragma unroll 8
    for (int d = 0; d < DEn; d += 4) {
        a0 = fmaf(Wd[(d + 0) * Cn + c], es[(d + 0) * 4 + ti], a0);
        a1 = fmaf(Wd[(d + 1) * Cn + c], es[(d + 1) * 4 + ti], a1);
        a2 = fmaf(Wd[(d + 2) * Cn + c], es[(d + 2) * 4 + ti], a2);
        a3 = fmaf(Wd[(d + 3) * Cn + c], es[(d + 3) * 4 + ti], a3);
    }
    float a = (a0 + a1) + (a2 + a3);
    g_et[b * Tn * Cn + t * Cn + c] = a;
    g_ec[b * Cn * Tn + c * Tn + t] = a;
}

// ---------------------------------------------------------------------------
// Kernel B: 512 threads, 2 CTAs/SM. Dynamic smem (floats), 25600 = 102400 B:
//   et @ 0     : [32][128]             4096
//   ec @ 4096  : [128][34]             4352   (f2 stride 17 -> conflict-free)
//   hs @ 8448  : [128][68] (c half)    8704   (f4 stride 17 -> conflict-free)
//   ss @ 17152 : [32][128]             4096
//   bt @ 21248 : [128][34]             4352
// ---------------------------------------------------------------------------
__global__ __launch_bounds__(512, 2) void ker_attn(const float* __restrict__ h,
                                                   float* __restrict__ out) {
    extern __shared__ float smem[];
    float* et = smem;          // [t][c]
    float* ec = smem + 4096;   // [c][t] stride 34
    float* hs = smem + 8448;   // [n][c-half] f4 stride 17
    float* ss = smem + 17152;  // [t][n] stride 128
    float* bt = smem + 21248;  // [n][t] stride 34

    int tid = threadIdx.x;
    int tile = blockIdx.x, b = blockIdx.y;
    size_t row0 = (size_t)b * HWn + (size_t)tile * NT;

    const float4* hg4 = (const float4*)(h + row0 * Cn);  // [n][32 f4]
    float4* hs4 = (float4*)hs;

    // ---- phase 0: stage e_ (both layouts) + h chunk 0 ----
    const float* etg = g_et + b * (Tn * Cn);
    const float* ecg = g_ec + b * (Cn * Tn);
    for (int i = tid; i < Tn * Cn; i += 512) {
        et[i] = etg[i];
        ec[(i >> 5) * 34 + (i & 31)] = ecg[i];
    }
#pragma unroll
    for (int it = 0; it < 4; it++) {
        int i = it * 512 + tid;           // 0..2047
        int n = i >> 4, c4 = i & 15;
        hs4[n * 17 + c4] = hg4[n * 32 + c4];
    }
    __syncthreads();

    // ---- phase 1: s GEMM: 16 warps, 2t x 4n(f32x2) per thread, f4 c-pairs ----
    const float4* et4 = (const float4*)et;  // [t][32 f4]
    int nq = tid & 31;
    int t0 = (tid >> 5) * 2;
    float2 acc[2][4];
#pragma unroll
    for (int i = 0; i < 2; i++)
#pragma unroll
        for (int j = 0; j < 4; j++) acc[i][j] = make_float2(0.f, 0.f);

#pragma unroll
    for (int r = 0; r < 2; r++) {
        if (r) {
            __syncthreads();
#pragma unroll
            for (int it = 0; it < 4; it++) {
                int i = it * 512 + tid;
                int n = i >> 4, c4 = i & 15;
                hs4[n * 17 + c4] = hg4[n * 32 + 16 + c4];
            }
            __syncthreads();
        }
#pragma unroll 4
        for (int c4 = 0; c4 < 16; c4++) {
            float4 ev0 = et4[(t0 + 0) * 32 + r * 16 + c4];
            float4 ev1 = et4[(t0 + 1) * 32 + r * 16 + c4];
            float4 hv[4];
#pragma unroll
            for (int j = 0; j < 4; j++) hv[j] = hs4[(nq + 32 * j) * 17 + c4];
#pragma unroll
            for (int j = 0; j < 4; j++) {
                acc[0][j] = ffma2(make_float2(ev0.x, ev0.y),
                                  make_float2(hv[j].x, hv[j].y), acc[0][j]);
                acc[0][j] = ffma2(make_float2(ev0.z, ev0.w),
                                  make_float2(hv[j].z, hv[j].w), acc[0][j]);
                acc[1][j] = ffma2(make_float2(ev1.x, ev1.y),
                                  make_float2(hv[j].x, hv[j].y), acc[1][j]);
                acc[1][j] = ffma2(make_float2(ev1.z, ev1.w),
                                  make_float2(hv[j].z, hv[j].w), acc[1][j]);
            }
        }
    }
#pragma unroll
    for (int i = 0; i < 2; i++)
#pragma unroll
        for (int j = 0; j < 4; j++)
            ss[(t0 + i) * 128 + nq + 32 * j] = acc[i][j].x + acc[i][j].y;
    __syncthreads();

    // ---- phase 2: softmax (tid<128) | h->out copy rows 0..95 (tid>=128) ----
    float4* out4 = (float4*)out;
    if (tid < 128) {
        int n = tid;
        float m = -1e30f;
#pragma unroll
        for (int t = 0; t < Tn; t++) m = fmaxf(m, ss[t * 128 + n]);
        float sum = 0.f;
#pragma unroll
        for (int t = 0; t < Tn; t++) {
            float ev = __expf(ss[t * 128 + n] - m);
            bt[n * 34 + t] = ev;
            sum += ev;
        }
        float r = __fdividef(1.0f, sum);
#pragma unroll
        for (int t = 0; t < Tn; t++) bt[n * 34 + t] *= r;
    } else {
        int k = tid - 128;  // 0..383
#pragma unroll
        for (int it = 0; it < 8; it++) {
            int i = it * 384 + k;  // 0..3071 -> n 0..95
            int n = i >> 5, q = i & 31;
            out4[(row0 + n) * 64 + 32 + q] = hg4[n * 32 + q];
        }
    }
    __syncthreads();

    // ---- phase 3: context GEMM: 4c x 4n(f32x2) per thread, 2 c-passes ----
    {
        const float2* ec2 = (const float2*)ec;  // stride 17 f2
        const float2* bt2 = (const float2*)bt;  // stride 17 f2
        int nh = tid & 31;
        int cq = tid >> 5;  // 0..15

#pragma unroll
        for (int pass = 0; pass < 2; pass++) {
            int cbase = pass * 64 + cq * 4;
            float2 a3[4][4];
#pragma unroll
            for (int i = 0; i < 4; i++)
#pragma unroll
                for (int j = 0; j < 4; j++) a3[i][j] = make_float2(0.f, 0.f);

#pragma unroll 4
            for (int t2 = 0; t2 < 16; t2++) {
                float2 ev[4], bv[4];
#pragma unroll
                for (int i = 0; i < 4; i++) ev[i] = ec2[(cbase + i) * 17 + t2];
#pragma unroll
                for (int j = 0; j < 4; j++) bv[j] = bt2[(nh + 32 * j) * 17 + t2];
#pragma unroll
                for (int i = 0; i < 4; i++)
#pragma unroll
                    for (int j = 0; j < 4; j++)
                        a3[i][j] = ffma2(ev[i], bv[j], a3[i][j]);
            }
#pragma unroll
            for (int j = 0; j < 4; j++) {
                int n = nh + 32 * j;
                float4 v;
                v.x = a3[0][j].x + a3[0][j].y;
                v.y = a3[1][j].x + a3[1][j].y;
                v.z = a3[2][j].x + a3[2][j].y;
                v.w = a3[3][j].x + a3[3][j].y;
                *(float4*)(out + (row0 + n) * 256 + cbase) = v;
            }
        }
    }

    // ---- phase 4: h copy rows 96..127 (all threads) ----
#pragma unroll
    for (int it = 0; it < 2; it++) {
        int i = it * 512 + tid;  // 0..1023
        int n = 96 + (i >> 5), q = i & 31;
        out4[(row0 + n) * 64 + 32 + q] = hg4[n * 32 + q];
    }
}

// ---------------------------------------------------------------------------
extern "C" void kernel_launch(void* const* d_in, const int* in_sizes, int n_in,
                              void* d_out, int out_size) {
    const float* e    = (const float*)d_in[0];
    const float* h    = (const float*)d_in[1];
    const float* Wd   = (const float*)d_in[2];
    const float* bias = (const float*)d_in[3];
    float* out = (float*)d_out;

    (void)in_sizes; (void)n_in; (void)out_size;

    cudaFuncSetAttribute(ker_attn, cudaFuncAttributeMaxDynamicSharedMemorySize,
                         102400);

    ker_e<<<dim3(8, Bn), 512>>>(e, Wd, bias);
    ker_attn<<<dim3(NTILES, Bn), 512, 102400>>>(h, out);
}

// round 6
// speedup vs baseline: 2.8972x; 2.0565x over previous
#include <cuda_runtime.h>
#include <cuda_bf16.h>
#include <cstdint>

#define Bn 32
#define DEn 256
#define Tn 32
#define Cn 128
#define HWn 16384
#define NT 128
#define NTILES (HWn / NT)

// bf16 hi/lo splits of the projection, both layouts
__device__ __align__(16) unsigned short g_et_hi[Bn * Tn * Cn];  // [b][t][c]
__device__ __align__(16) unsigned short g_et_lo[Bn * Tn * Cn];
__device__ __align__(16) unsigned short g_ec_hi[Bn * Cn * Tn];  // [b][c][t]
__device__ __align__(16) unsigned short g_ec_lo[Bn * Cn * Tn];

// smem byte offsets
#define SM_H_HI 0        // 128 rows x 256B, rotated chunks
#define SM_H_LO 32768
#define SM_ET_HI 65536   // 32 rows x 256B (overlaid later by ABUF)
#define SM_ET_LO 73728
#define SM_ABUF 65536    // [2][8][8][32] u32 = 16KB, overlays et
#define SM_EC_HI 81920   // 128 rows x 80B
#define SM_EC_LO 92160
#define SM_EXCH 102400   // [8][16][2] float2 = 2KB
#define SMEM_BYTES 104448

__device__ __forceinline__ void bsplit(float x, unsigned short& h,
                                       unsigned short& l) {
    __nv_bfloat16 hb = __float2bfloat16_rn(x);
    float hf = __bfloat162float(hb);
    __nv_bfloat16 lb = __float2bfloat16_rn(x - hf);
    h = *(unsigned short*)&hb;
    l = *(unsigned short*)&lb;
}
__device__ __forceinline__ uint32_t pkk(unsigned short lo, unsigned short hi) {
    return (uint32_t)lo | ((uint32_t)hi << 16);
}

__device__ __forceinline__ void mma16816(float d[4], uint32_t a0, uint32_t a1,
                                         uint32_t a2, uint32_t a3, uint32_t b0,
                                         uint32_t b1) {
    asm volatile(
        "mma.sync.aligned.m16n8k16.row.col.f32.bf16.bf16.f32 "
        "{%0,%1,%2,%3},{%4,%5,%6,%7},{%8,%9},{%0,%1,%2,%3};"
        : "+f"(d[0]), "+f"(d[1]), "+f"(d[2]), "+f"(d[3])
        : "r"(a0), "r"(a1), "r"(a2), "r"(a3), "r"(b0), "r"(b1));
}

// ---------------------------------------------------------------------------
// Kernel A: e_ = Wd^T e + b -> bf16 hi/lo, both layouts
// ---------------------------------------------------------------------------
__global__ __launch_bounds__(512) void ker_e(const float* __restrict__ e,
                                             const float* __restrict__ Wd,
                                             const float* __restrict__ bias) {
    __shared__ float es[DEn * 4];
    int tg = blockIdx.x, b = blockIdx.y;
    int tid = threadIdx.x;
    int c = tid & 127, ti = tid >> 7;
    int t = tg * 4 + ti;

    const float* eb = e + (size_t)b * DEn * Tn;
    for (int i = tid; i < DEn * 4; i += 512) {
        int d = i >> 2, tt = i & 3;
        es[i] = eb[d * Tn + tg * 4 + tt];
    }
    __syncthreads();

    float a0 = bias[c], a1 = 0.f, a2 = 0.f, a3 = 0.f;
#pragma unroll 8
    for (int d = 0; d < DEn; d += 4) {
        a0 = fmaf(Wd[(d + 0) * Cn + c], es[(d + 0) * 4 + ti], a0);
        a1 = fmaf(Wd[(d + 1) * Cn + c], es[(d + 1) * 4 + ti], a1);
        a2 = fmaf(Wd[(d + 2) * Cn + c], es[(d + 2) * 4 + ti], a2);
        a3 = fmaf(Wd[(d + 3) * Cn + c], es[(d + 3) * 4 + ti], a3);
    }
    float a = (a0 + a1) + (a2 + a3);
    unsigned short hh, ll;
    bsplit(a, hh, ll);
    g_et_hi[b * Tn * Cn + t * Cn + c] = hh;
    g_et_lo[b * Tn * Cn + t * Cn + c] = ll;
    g_ec_hi[b * Cn * Tn + c * Tn + t] = hh;
    g_ec_lo[b * Cn * Tn + c * Tn + t] = ll;
}

// rotated-chunk address for 256B rows
__device__ __forceinline__ int radr(int row, int chunk) {
    return row * 256 + (((chunk) + row) & 15) * 16;
}

// ---------------------------------------------------------------------------
// Kernel B: mma.sync bf16-split attention tile. 512 threads, 2 CTAs/SM.
// ---------------------------------------------------------------------------
__global__ __launch_bounds__(512, 2) void ker_attn(const float* __restrict__ h,
                                                   float* __restrict__ out) {
    extern __shared__ char sm[];
    int tid = threadIdx.x;
    int lane = tid & 31, wid = tid >> 5;
    int tile = blockIdx.x, b = blockIdx.y;
    size_t row0 = (size_t)b * HWn + (size_t)tile * NT;

    // ---- stage h (hi/lo bf16, rotated) + pass-through copy ----
    const float4* hg = (const float4*)(h + row0 * Cn);
    float4* outg = (float4*)out;
#pragma unroll
    for (int it = 0; it < 4; it++) {
        int idx = it * 512 + tid;
        int n = idx >> 4, ch = idx & 15;
        float4 v0 = hg[n * 32 + ch * 2];
        float4 v1 = hg[n * 32 + ch * 2 + 1];
        outg[(row0 + n) * 64 + 32 + ch * 2] = v0;
        outg[(row0 + n) * 64 + 32 + ch * 2 + 1] = v1;
        unsigned short h0, l0, h1, l1, h2, l2, h3, l3;
        unsigned short h4, l4, h5, l5, h6, l6, h7, l7;
        bsplit(v0.x, h0, l0); bsplit(v0.y, h1, l1);
        bsplit(v0.z, h2, l2); bsplit(v0.w, h3, l3);
        bsplit(v1.x, h4, l4); bsplit(v1.y, h5, l5);
        bsplit(v1.z, h6, l6); bsplit(v1.w, h7, l7);
        uint4 hv, lv;
        hv.x = pkk(h0, h1); hv.y = pkk(h2, h3);
        hv.z = pkk(h4, h5); hv.w = pkk(h6, h7);
        lv.x = pkk(l0, l1); lv.y = pkk(l2, l3);
        lv.z = pkk(l4, l5); lv.w = pkk(l6, l7);
        int dst = radr(n, ch);
        *(uint4*)(sm + SM_H_HI + dst) = hv;
        *(uint4*)(sm + SM_H_LO + dst) = lv;
    }
    // ---- stage et (hi/lo) rotated ----
    {
        int t = tid >> 4, ch = tid & 15;
        const uint4* eth = (const uint4*)(g_et_hi + (size_t)b * Tn * Cn);
        const uint4* etl = (const uint4*)(g_et_lo + (size_t)b * Tn * Cn);
        int dst = radr(t, ch);
        *(uint4*)(sm + SM_ET_HI + dst) = eth[t * 16 + ch];
        *(uint4*)(sm + SM_ET_LO + dst) = etl[t * 16 + ch];
    }
    // ---- stage ec (hi/lo), 80B padded rows ----
    {
        int c = tid >> 2, ch = tid & 3;
        const uint4* ech = (const uint4*)(g_ec_hi + (size_t)b * Cn * Tn);
        const uint4* ecl = (const uint4*)(g_ec_lo + (size_t)b * Cn * Tn);
        int dst = c * 80 + ch * 16;
        *(uint4*)(sm + SM_EC_HI + dst) = ech[c * 4 + ch];
        *(uint4*)(sm + SM_EC_LO + dst) = ecl[c * 4 + ch];
    }
    __syncthreads();

    int mt = wid >> 1, th = wid & 1;
    int g = lane >> 2, tig = lane & 3;
    int rA = mt * 16 + g;   // A row (spatial n)
    int tB = th * 16 + g;   // B row (t), tiles at +0 / +8

    // ---- GEMM1: D1[n][t] = sum_c h.et, bf16 3-product split ----
    float d0[4] = {0.f, 0.f, 0.f, 0.f};
    float d1[4] = {0.f, 0.f, 0.f, 0.f};
#pragma unroll
    for (int ks = 0; ks < 8; ks++) {
        int c0 = 2 * ks, c1 = 2 * ks + 1;
        int o = 4 * tig;
        uint32_t ahi[4], alo[4];
        ahi[0] = *(const uint32_t*)(sm + SM_H_HI + radr(rA, c0) + o);
        ahi[1] = *(const uint32_t*)(sm + SM_H_HI + radr(rA + 8, c0) + o);
        ahi[2] = *(const uint32_t*)(sm + SM_H_HI + radr(rA, c1) + o);
        ahi[3] = *(const uint32_t*)(sm + SM_H_HI + radr(rA + 8, c1) + o);
        alo[0] = *(const uint32_t*)(sm + SM_H_LO + radr(rA, c0) + o);
        alo[1] = *(const uint32_t*)(sm + SM_H_LO + radr(rA + 8, c0) + o);
        alo[2] = *(const uint32_t*)(sm + SM_H_LO + radr(rA, c1) + o);
        alo[3] = *(const uint32_t*)(sm + SM_H_LO + radr(rA + 8, c1) + o);
        uint32_t bh0[2], bh1[2], bl0[2], bl1[2];
        bh0[0] = *(const uint32_t*)(sm + SM_ET_HI + radr(tB, c0) + o);
        bh0[1] = *(const uint32_t*)(sm + SM_ET_HI + radr(tB, c1) + o);
        bh1[0] = *(const uint32_t*)(sm + SM_ET_HI + radr(tB + 8, c0) + o);
        bh1[1] = *(const uint32_t*)(sm + SM_ET_HI + radr(tB + 8, c1) + o);
        bl0[0] = *(const uint32_t*)(sm + SM_ET_LO + radr(tB, c0) + o);
        bl0[1] = *(const uint32_t*)(sm + SM_ET_LO + radr(tB, c1) + o);
        bl1[0] = *(const uint32_t*)(sm + SM_ET_LO + radr(tB + 8, c0) + o);
        bl1[1] = *(const uint32_t*)(sm + SM_ET_LO + radr(tB + 8, c1) + o);
        mma16816(d0, ahi[0], ahi[1], ahi[2], ahi[3], bh0[0], bh0[1]);
        mma16816(d0, ahi[0], ahi[1], ahi[2], ahi[3], bl0[0], bl0[1]);
        mma16816(d0, alo[0], alo[1], alo[2], alo[3], bh0[0], bh0[1]);
        mma16816(d1, ahi[0], ahi[1], ahi[2], ahi[3], bh1[0], bh1[1]);
        mma16816(d1, ahi[0], ahi[1], ahi[2], ahi[3], bl1[0], bl1[1]);
        mma16816(d1, alo[0], alo[1], alo[2], alo[3], bh1[0], bh1[1]);
    }

    // ---- softmax over t (in fragments) ----
    // row g    values: d0[0],d0[1] (t=16th+2tig,+1), d1[0],d1[1] (t=16th+8+2tig,+1)
    // row g+8  values: d0[2],d0[3],                  d1[2],d1[3]
    float mA = fmaxf(fmaxf(d0[0], d0[1]), fmaxf(d1[0], d1[1]));
    float mB = fmaxf(fmaxf(d0[2], d0[3]), fmaxf(d1[2], d1[3]));
#pragma unroll
    for (int o = 1; o <= 2; o <<= 1) {
        mA = fmaxf(mA, __shfl_xor_sync(0xffffffffu, mA, o));
        mB = fmaxf(mB, __shfl_xor_sync(0xffffffffu, mB, o));
    }
    float eA0 = __expf(d0[0] - mA), eA1 = __expf(d0[1] - mA);
    float eA2 = __expf(d1[0] - mA), eA3 = __expf(d1[1] - mA);
    float eB0 = __expf(d0[2] - mB), eB1 = __expf(d0[3] - mB);
    float eB2 = __expf(d1[2] - mB), eB3 = __expf(d1[3] - mB);
    float sA = (eA0 + eA1) + (eA2 + eA3);
    float sB = (eB0 + eB1) + (eB2 + eB3);
#pragma unroll
    for (int o = 1; o <= 2; o <<= 1) {
        sA += __shfl_xor_sync(0xffffffffu, sA, o);
        sB += __shfl_xor_sync(0xffffffffu, sB, o);
    }
    float2* exch = (float2*)(sm + SM_EXCH);
    if (tig == 0) {
        exch[(mt * 16 + g) * 2 + th] = make_float2(mA, sA);
        exch[(mt * 16 + g + 8) * 2 + th] = make_float2(mB, sB);
    }
    __syncthreads();  // also: GEMM1 et reads done -> ABUF overlay safe
    float2 pA = exch[(mt * 16 + g) * 2 + (1 - th)];
    float2 pB = exch[(mt * 16 + g + 8) * 2 + (1 - th)];
    float MA = fmaxf(mA, pA.x);
    float SA = sA * __expf(mA - MA) + pA.y * __expf(pA.x - MA);
    float scA = __fdividef(__expf(mA - MA), SA);
    float MB = fmaxf(mB, pB.x);
    float SB = sB * __expf(mB - MB) + pB.y * __expf(pB.x - MB);
    float scB = __fdividef(__expf(mB - MB), SB);

    // pack own A-fragments for GEMM2 kstep=th  (a0..a3 layout == c-frag layout)
    uint32_t oa[8];  // 0..3 hi, 4..7 lo
    {
        unsigned short x0, y0, x1, y1;
        bsplit(eA0 * scA, x0, y0); bsplit(eA1 * scA, x1, y1);
        oa[0] = pkk(x0, x1); oa[4] = pkk(y0, y1);
        bsplit(eB0 * scB, x0, y0); bsplit(eB1 * scB, x1, y1);
        oa[1] = pkk(x0, x1); oa[5] = pkk(y0, y1);
        bsplit(eA2 * scA, x0, y0); bsplit(eA3 * scA, x1, y1);
        oa[2] = pkk(x0, x1); oa[6] = pkk(y0, y1);
        bsplit(eB2 * scB, x0, y0); bsplit(eB3 * scB, x1, y1);
        oa[3] = pkk(x0, x1); oa[7] = pkk(y0, y1);
    }
#pragma unroll
    for (int r = 0; r < 8; r++)
        *(uint32_t*)(sm + SM_ABUF +
                     ((((th * 8 + mt) * 8) + r) * 32 + lane) * 4) = oa[r];
    __syncthreads();
    uint32_t pa[8];
#pragma unroll
    for (int r = 0; r < 8; r++)
        pa[r] = *(const uint32_t*)(sm + SM_ABUF +
                                   (((((1 - th) * 8 + mt) * 8) + r) * 32 + lane) * 4);

    // ---- GEMM2: D2[n][c] = sum_t beta.ec, 3-product split ----
    // warp covers m16 rows (mt), c-half th (64 cols) in 2 passes of 32
#pragma unroll
    for (int pass = 0; pass < 2; pass++) {
        float d[4][4];
#pragma unroll
        for (int i = 0; i < 4; i++)
#pragma unroll
            for (int j = 0; j < 4; j++) d[i][j] = 0.f;
#pragma unroll
        for (int ks = 0; ks < 2; ks++) {
            const uint32_t* af = (ks == th) ? oa : pa;
#pragma unroll
            for (int tl = 0; tl < 4; tl++) {
                int crow = th * 64 + pass * 32 + tl * 8 + g;
                int ob = crow * 80 + 32 * ks + 4 * tig;
                uint32_t b0h = *(const uint32_t*)(sm + SM_EC_HI + ob);
                uint32_t b1h = *(const uint32_t*)(sm + SM_EC_HI + ob + 16);
                uint32_t b0l = *(const uint32_t*)(sm + SM_EC_LO + ob);
                uint32_t b1l = *(const uint32_t*)(sm + SM_EC_LO + ob + 16);
                mma16816(d[tl], af[0], af[1], af[2], af[3], b0h, b1h);
                mma16816(d[tl], af[0], af[1], af[2], af[3], b0l, b1l);
                mma16816(d[tl], af[4], af[5], af[6], af[7], b0h, b1h);
            }
        }
#pragma unroll
        for (int tl = 0; tl < 4; tl++) {
            int col = th * 64 + pass * 32 + tl * 8 + 2 * tig;
            int n0 = mt * 16 + g;
            *(float2*)(out + (row0 + n0) * 256 + col) =
                make_float2(d[tl][0], d[tl][1]);
            *(float2*)(out + (row0 + n0 + 8) * 256 + col) =
                make_float2(d[tl][2], d[tl][3]);
        }
    }
}

// ---------------------------------------------------------------------------
extern "C" void kernel_launch(void* const* d_in, const int* in_sizes, int n_in,
                              void* d_out, int out_size) {
    const float* e    = (const float*)d_in[0];  // [B, DE, T]
    const float* h    = (const float*)d_in[1];  // [B, H, W, C]
    const float* Wd   = (const float*)d_in[2];  // [DE, C]
    const float* bias = (const float*)d_in[3];  // [C]
    float* out = (float*)d_out;                 // [B, H, W, 2C]

    (void)in_sizes; (void)n_in; (void)out_size;

    cudaFuncSetAttribute(ker_attn, cudaFuncAttributeMaxDynamicSharedMemorySize,
                         SMEM_BYTES);

    ker_e<<<dim3(8, Bn), 512>>>(e, Wd, bias);
    ker_attn<<<dim3(NTILES, Bn), 512, SMEM_BYTES>>>(h, out);
}

// round 7
// speedup vs baseline: 3.1512x; 1.0877x over previous
#include <cuda_runtime.h>
#include <cuda_bf16.h>
#include <cstdint>

#define Bn 32
#define DEn 256
#define Tn 32
#define Cn 128
#define HWn 16384
#define NT 128
#define NTILES (HWn / NT)

// bf16 hi/lo splits of the projection, both layouts
__device__ __align__(16) unsigned short g_et_hi[Bn * Tn * Cn];  // [b][t][c]
__device__ __align__(16) unsigned short g_et_lo[Bn * Tn * Cn];
__device__ __align__(16) unsigned short g_ec_hi[Bn * Cn * Tn];  // [b][c][t]
__device__ __align__(16) unsigned short g_ec_lo[Bn * Cn * Tn];

// ker_attn smem byte offsets
#define SM_ET_HI 0        // 32 rows x 256B rotated
#define SM_ET_LO 8192
#define SM_EC_HI 16384    // 128 rows x 80B
#define SM_EC_LO 26624
#define SM_ABUF 36864     // 8 warps x 16 regs x 32 lanes x 4B = 16KB
#define SMEM_BYTES 53248

__device__ __forceinline__ void bsplit(float x, unsigned short& h,
                                       unsigned short& l) {
    __nv_bfloat16 hb = __float2bfloat16_rn(x);
    float hf = __bfloat162float(hb);
    __nv_bfloat16 lb = __float2bfloat16_rn(x - hf);
    h = *(unsigned short*)&hb;
    l = *(unsigned short*)&lb;
}
__device__ __forceinline__ uint32_t pkk(unsigned short lo, unsigned short hi) {
    return (uint32_t)lo | ((uint32_t)hi << 16);
}
// split a float2 into packed-bf16 hi and lo words
__device__ __forceinline__ void bsplit2(float2 v, uint32_t& hw, uint32_t& lw) {
    unsigned short h0, l0, h1, l1;
    bsplit(v.x, h0, l0);
    bsplit(v.y, h1, l1);
    hw = pkk(h0, h1);
    lw = pkk(l0, l1);
}

__device__ __forceinline__ void mma16816(float d[4], uint32_t a0, uint32_t a1,
                                         uint32_t a2, uint32_t a3, uint32_t b0,
                                         uint32_t b1) {
    asm volatile(
        "mma.sync.aligned.m16n8k16.row.col.f32.bf16.bf16.f32 "
        "{%0,%1,%2,%3},{%4,%5,%6,%7},{%8,%9},{%0,%1,%2,%3};"
        : "+f"(d[0]), "+f"(d[1]), "+f"(d[2]), "+f"(d[3])
        : "r"(a0), "r"(a1), "r"(a2), "r"(a3), "r"(b0), "r"(b1));
}

// rotated-chunk address for 256B rows
__device__ __forceinline__ int radr(int row, int chunk) {
    return row * 256 + (((chunk) + row) & 15) * 16;
}

// ---------------------------------------------------------------------------
// Kernel A: e_ = Wd^T e + b -> bf16 hi/lo, both layouts, coalesced stores.
// grid (4 c-quarters, B), 512 threads.
// ---------------------------------------------------------------------------
__global__ __launch_bounds__(512) void ker_e(const float* __restrict__ e,
                                             const float* __restrict__ Wd,
                                             const float* __restrict__ bias) {
    __shared__ float es[DEn * Tn];    // [d][t] 32KB
    __shared__ uint32_t pk[32 * 33];  // [c_local][t] hi|lo<<16, padded
    int cq = blockIdx.x, b = blockIdx.y;
    int tid = threadIdx.x;
    int c = tid & 31, tp = tid >> 5;  // c local, t-pair 0..15

    const float* eb = e + (size_t)b * DEn * Tn;
    for (int i = tid; i < DEn * Tn; i += 512) es[i] = eb[i];
    __syncthreads();

    int cg = cq * 32 + c;
    float bv = bias[cg];
    float a0 = bv, a1 = bv;
#pragma unroll 8
    for (int d = 0; d < DEn; d++) {
        float w = Wd[d * Cn + cg];
        a0 = fmaf(w, es[d * Tn + 2 * tp], a0);
        a1 = fmaf(w, es[d * Tn + 2 * tp + 1], a1);
    }
    unsigned short h0, l0, h1, l1;
    bsplit(a0, h0, l0);
    bsplit(a1, h1, l1);
    pk[c * 33 + 2 * tp] = (uint32_t)h0 | ((uint32_t)l0 << 16);
    pk[c * 33 + 2 * tp + 1] = (uint32_t)h1 | ((uint32_t)l1 << 16);
    __syncthreads();

    // et arrays: [t][c] rows, u32 = c-pair
    {
        int t = tid >> 4, cp = tid & 15;
        uint32_t v0 = pk[(2 * cp) * 33 + t], v1 = pk[(2 * cp + 1) * 33 + t];
        uint32_t hi = (v0 & 0xFFFFu) | ((v1 & 0xFFFFu) << 16);
        uint32_t lo = (v0 >> 16) | ((v1 >> 16) << 16);
        size_t base = (size_t)b * Tn * Cn + t * Cn + cq * 32;
        ((uint32_t*)(g_et_hi + base))[cp] = hi;
        ((uint32_t*)(g_et_lo + base))[cp] = lo;
    }
    // ec arrays: [c][t] rows, u32 = t-pair
    {
        int cL = tid >> 4, tp2 = tid & 15;
        uint32_t v0 = pk[cL * 33 + 2 * tp2], v1 = pk[cL * 33 + 2 * tp2 + 1];
        uint32_t hi = (v0 & 0xFFFFu) | ((v1 & 0xFFFFu) << 16);
        uint32_t lo = (v0 >> 16) | ((v1 >> 16) << 16);
        size_t base = (size_t)b * Cn * Tn + (size_t)(cq * 32 + cL) * Tn;
        ((uint32_t*)(g_ec_hi + base))[tp2] = hi;
        ((uint32_t*)(g_ec_lo + base))[tp2] = lo;
    }
}

// ---------------------------------------------------------------------------
// Kernel B: warp-specialized mma.sync attention tile. 512 thr, 2 CTAs/SM.
//   warps 0-7  (compute): GEMM1 (A from gmem, B=et smem), softmax, ABUF, GEMM2
//   warps 8-15 (copy): stage et/ec, h->out passthrough, GEMM2 (beta via ABUF)
// ---------------------------------------------------------------------------
__global__ __launch_bounds__(512, 2) void ker_attn(const float* __restrict__ h,
                                                   float* __restrict__ out) {
    extern __shared__ char sm[];
    int tid = threadIdx.x;
    int lane = tid & 31, wid = tid >> 5;
    int g = lane >> 2, tig = lane & 3;
    int tile = blockIdx.x, b = blockIdx.y;
    size_t row0 = (size_t)b * HWn + (size_t)tile * NT;

    float2 buf[4];
    const float* hrow0 = 0;
    const float* hrow8 = 0;

    if (wid >= 8) {
        // ---- copy warps: stage et + ec into smem ----
        int ct = tid - 256;
        const uint4* eth = (const uint4*)(g_et_hi + (size_t)b * Tn * Cn);
        const uint4* etl = (const uint4*)(g_et_lo + (size_t)b * Tn * Cn);
#pragma unroll
        for (int it = 0; it < 2; it++) {
            int idx = it * 256 + ct;
            int t = idx >> 4, ch = idx & 15;
            int dst = radr(t, ch);
            *(uint4*)(sm + SM_ET_HI + dst) = eth[idx];
            *(uint4*)(sm + SM_ET_LO + dst) = etl[idx];
        }
        const uint4* ech = (const uint4*)(g_ec_hi + (size_t)b * Cn * Tn);
        const uint4* ecl = (const uint4*)(g_ec_lo + (size_t)b * Cn * Tn);
#pragma unroll
        for (int it = 0; it < 2; it++) {
            int idx = it * 256 + ct;
            int c = idx >> 2, ch = idx & 3;
            int dst = c * 80 + ch * 16;
            *(uint4*)(sm + SM_EC_HI + dst) = ech[idx];
            *(uint4*)(sm + SM_EC_LO + dst) = ecl[idx];
        }
    } else {
        // ---- compute warps: prefetch A kstep 0 from gmem ----
        int rA = wid * 16 + g;
        hrow0 = h + (row0 + rA) * Cn;
        hrow8 = h + (row0 + rA + 8) * Cn;
        buf[0] = *(const float2*)(hrow0 + 2 * tig);
        buf[1] = *(const float2*)(hrow0 + 8 + 2 * tig);
        buf[2] = *(const float2*)(hrow8 + 2 * tig);
        buf[3] = *(const float2*)(hrow8 + 8 + 2 * tig);
    }
    __syncthreads();  // (1) et/ec staged

    uint32_t af[16];  // beta A-fragments: [ks2][0..3 hi, 4..7 lo]

    if (wid < 8) {
        // ---- GEMM1: D1[n][t] = sum_c h.et, 3-product bf16 split ----
        float d[4][4];
#pragma unroll
        for (int i = 0; i < 4; i++)
#pragma unroll
            for (int j = 0; j < 4; j++) d[i][j] = 0.f;

#pragma unroll
        for (int ks = 0; ks < 8; ks++) {
            float2 cur[4];
#pragma unroll
            for (int i = 0; i < 4; i++) cur[i] = buf[i];
            if (ks < 7) {
                int cc = 16 * (ks + 1) + 2 * tig;
                buf[0] = *(const float2*)(hrow0 + cc);
                buf[1] = *(const float2*)(hrow0 + 8 + cc);
                buf[2] = *(const float2*)(hrow8 + cc);
                buf[3] = *(const float2*)(hrow8 + 8 + cc);
            }
            uint32_t ahi[4], alo[4];
            bsplit2(cur[0], ahi[0], alo[0]);  // row g,  k-low
            bsplit2(cur[2], ahi[1], alo[1]);  // row g+8, k-low
            bsplit2(cur[1], ahi[2], alo[2]);  // row g,  k-high
            bsplit2(cur[3], ahi[3], alo[3]);  // row g+8, k-high
            int c0 = 2 * ks, c1 = 2 * ks + 1, o = 4 * tig;
#pragma unroll
            for (int tt = 0; tt < 4; tt++) {
                int tB = tt * 8 + g;
                uint32_t bh0 = *(const uint32_t*)(sm + SM_ET_HI + radr(tB, c0) + o);
                uint32_t bh1 = *(const uint32_t*)(sm + SM_ET_HI + radr(tB, c1) + o);
                uint32_t bl0 = *(const uint32_t*)(sm + SM_ET_LO + radr(tB, c0) + o);
                uint32_t bl1 = *(const uint32_t*)(sm + SM_ET_LO + radr(tB, c1) + o);
                mma16816(d[tt], ahi[0], ahi[1], ahi[2], ahi[3], bh0, bh1);
                mma16816(d[tt], ahi[0], ahi[1], ahi[2], ahi[3], bl0, bl1);
                mma16816(d[tt], alo[0], alo[1], alo[2], alo[3], bh0, bh1);
            }
        }

        // ---- softmax over t, fully warp-local ----
        // row g: d[tt][0],d[tt][1] (t = 8tt+2tig+{0,1}); row g+8: d[tt][2],d[tt][3]
        float mA = -1e30f, mB = -1e30f;
#pragma unroll
        for (int tt = 0; tt < 4; tt++) {
            mA = fmaxf(mA, fmaxf(d[tt][0], d[tt][1]));
            mB = fmaxf(mB, fmaxf(d[tt][2], d[tt][3]));
        }
#pragma unroll
        for (int o = 1; o <= 2; o <<= 1) {
            mA = fmaxf(mA, __shfl_xor_sync(0xffffffffu, mA, o));
            mB = fmaxf(mB, __shfl_xor_sync(0xffffffffu, mB, o));
        }
        float sA = 0.f, sB = 0.f;
#pragma unroll
        for (int tt = 0; tt < 4; tt++) {
            d[tt][0] = __expf(d[tt][0] - mA);
            d[tt][1] = __expf(d[tt][1] - mA);
            d[tt][2] = __expf(d[tt][2] - mB);
            d[tt][3] = __expf(d[tt][3] - mB);
            sA += d[tt][0] + d[tt][1];
            sB += d[tt][2] + d[tt][3];
        }
#pragma unroll
        for (int o = 1; o <= 2; o <<= 1) {
            sA += __shfl_xor_sync(0xffffffffu, sA, o);
            sB += __shfl_xor_sync(0xffffffffu, sB, o);
        }
        float invA = __fdividef(1.0f, sA);
        float invB = __fdividef(1.0f, sB);

        // ---- pack beta A-fragments for both GEMM2 ksteps ----
#pragma unroll
        for (int ks2 = 0; ks2 < 2; ks2++) {
            unsigned short x0, y0, x1, y1;
            // a0: row g, t=16ks2+2tig,+1 -> d[2ks2][0..1]
            bsplit(d[2 * ks2][0] * invA, x0, y0);
            bsplit(d[2 * ks2][1] * invA, x1, y1);
            af[ks2 * 8 + 0] = pkk(x0, x1);
            af[ks2 * 8 + 4] = pkk(y0, y1);
            // a1: row g+8 -> d[2ks2][2..3]
            bsplit(d[2 * ks2][2] * invB, x0, y0);
            bsplit(d[2 * ks2][3] * invB, x1, y1);
            af[ks2 * 8 + 1] = pkk(x0, x1);
            af[ks2 * 8 + 5] = pkk(y0, y1);
            // a2: row g, t=16ks2+8+2tig -> d[2ks2+1][0..1]
            bsplit(d[2 * ks2 + 1][0] * invA, x0, y0);
            bsplit(d[2 * ks2 + 1][1] * invA, x1, y1);
            af[ks2 * 8 + 2] = pkk(x0, x1);
            af[ks2 * 8 + 6] = pkk(y0, y1);
            // a3: row g+8 -> d[2ks2+1][2..3]
            bsplit(d[2 * ks2 + 1][2] * invB, x0, y0);
            bsplit(d[2 * ks2 + 1][3] * invB, x1, y1);
            af[ks2 * 8 + 3] = pkk(x0, x1);
            af[ks2 * 8 + 7] = pkk(y0, y1);
        }
        // publish to ABUF for the copy-warp twin
#pragma unroll
        for (int r = 0; r < 16; r++)
            *(uint32_t*)(sm + SM_ABUF + ((wid * 16 + r) * 32 + lane) * 4) = af[r];
    } else {
        // ---- copy warps: h -> out passthrough (runs during GEMM1) ----
        const float4* hg = (const float4*)(h + row0 * Cn);
        float4* outg = (float4*)out;
        int ct = tid - 256;
#pragma unroll
        for (int it = 0; it < 16; it++) {
            int idx = it * 256 + ct;
            int n = idx >> 5, q = idx & 31;
            outg[(row0 + n) * 64 + 32 + q] = hg[idx];
        }
    }
    __syncthreads();  // (2) ABUF ready

    if (wid >= 8) {
#pragma unroll
        for (int r = 0; r < 16; r++)
            af[r] = *(const uint32_t*)(sm + SM_ABUF +
                                       (((wid - 8) * 16 + r) * 32 + lane) * 4);
    }

    // ---- GEMM2: D2[n][c] = sum_t beta.ec, 3-product split ----
    int mt = wid & 7, th = wid >> 3;
    int n0 = mt * 16 + g;
#pragma unroll
    for (int pass = 0; pass < 2; pass++) {
        float d2[4][4];
#pragma unroll
        for (int i = 0; i < 4; i++)
#pragma unroll
            for (int j = 0; j < 4; j++) d2[i][j] = 0.f;
#pragma unroll
        for (int ks2 = 0; ks2 < 2; ks2++) {
            const uint32_t* a = af + ks2 * 8;
#pragma unroll
            for (int tl = 0; tl < 4; tl++) {
                int crow = th * 64 + pass * 32 + tl * 8 + g;
                int ob = crow * 80 + 32 * ks2 + 4 * tig;
                uint32_t b0h = *(const uint32_t*)(sm + SM_EC_HI + ob);
                uint32_t b1h = *(const uint32_t*)(sm + SM_EC_HI + ob + 16);
                uint32_t b0l = *(const uint32_t*)(sm + SM_EC_LO + ob);
                uint32_t b1l = *(const uint32_t*)(sm + SM_EC_LO + ob + 16);
                mma16816(d2[tl], a[0], a[1], a[2], a[3], b0h, b1h);
                mma16816(d2[tl], a[0], a[1], a[2], a[3], b0l, b1l);
                mma16816(d2[tl], a[4], a[5], a[6], a[7], b0h, b1h);
            }
        }
#pragma unroll
        for (int tl = 0; tl < 4; tl++) {
            int col = th * 64 + pass * 32 + tl * 8 + 2 * tig;
            *(float2*)(out + (row0 + n0) * 256 + col) =
                make_float2(d2[tl][0], d2[tl][1]);
            *(float2*)(out + (row0 + n0 + 8) * 256 + col) =
                make_float2(d2[tl][2], d2[tl][3]);
        }
    }
}

// ---------------------------------------------------------------------------
extern "C" void kernel_launch(void* const* d_in, const int* in_sizes, int n_in,
                              void* d_out, int out_size) {
    const float* e    = (const float*)d_in[0];  // [B, DE, T]
    const float* h    = (const float*)d_in[1];  // [B, H, W, C]
    const float* Wd   = (const float*)d_in[2];  // [DE, C]
    const float* bias = (const float*)d_in[3];  // [C]
    float* out = (float*)d_out;                 // [B, H, W, 2C]

    (void)in_sizes; (void)n_in; (void)out_size;

    cudaFuncSetAttribute(ker_attn, cudaFuncAttributeMaxDynamicSharedMemorySize,
                         SMEM_BYTES);

    ker_e<<<dim3(4, Bn), 512>>>(e, Wd, bias);
    ker_attn<<<dim3(NTILES, Bn), 512, SMEM_BYTES>>>(h, out);
}

// round 8
// speedup vs baseline: 3.1571x; 1.0019x over previous
#include <cuda_runtime.h>
#include <cuda_bf16.h>
#include <cstdint>

#define Bn 32
#define DEn 256
#define Tn 32
#define Cn 128
#define HWn 16384
#define NT 128
#define NTILES (HWn / NT)

// bf16 hi/lo splits of the projection, both layouts
__device__ __align__(16) unsigned short g_et_hi[Bn * Tn * Cn];  // [b][t][c]
__device__ __align__(16) unsigned short g_et_lo[Bn * Tn * Cn];
__device__ __align__(16) unsigned short g_ec_hi[Bn * Cn * Tn];  // [b][c][t]
__device__ __align__(16) unsigned short g_ec_lo[Bn * Cn * Tn];

// ker_attn smem byte offsets
#define SM_ET_HI 0        // 32 rows x 256B rotated
#define SM_ET_LO 8192
#define SM_EC_HI 16384    // 128 rows x 80B
#define SM_EC_LO 26624
#define SM_ABUF 36864     // 8 warps x 16 regs x 32 lanes x 4B = 16KB
#define SMEM_BYTES 53248

__device__ __forceinline__ void bsplit(float x, unsigned short& h,
                                       unsigned short& l) {
    __nv_bfloat16 hb = __float2bfloat16_rn(x);
    float hf = __bfloat162float(hb);
    __nv_bfloat16 lb = __float2bfloat16_rn(x - hf);
    h = *(unsigned short*)&hb;
    l = *(unsigned short*)&lb;
}
__device__ __forceinline__ uint32_t pkk(unsigned short lo, unsigned short hi) {
    return (uint32_t)lo | ((uint32_t)hi << 16);
}
// split a float2 into packed-bf16 hi and lo words
__device__ __forceinline__ void bsplit2(float2 v, uint32_t& hw, uint32_t& lw) {
    unsigned short h0, l0, h1, l1;
    bsplit(v.x, h0, l0);
    bsplit(v.y, h1, l1);
    hw = pkk(h0, h1);
    lw = pkk(l0, l1);
}

__device__ __forceinline__ void mma16816(float d[4], uint32_t a0, uint32_t a1,
                                         uint32_t a2, uint32_t a3, uint32_t b0,
                                         uint32_t b1) {
    asm volatile(
        "mma.sync.aligned.m16n8k16.row.col.f32.bf16.bf16.f32 "
        "{%0,%1,%2,%3},{%4,%5,%6,%7},{%8,%9},{%0,%1,%2,%3};"
        : "+f"(d[0]), "+f"(d[1]), "+f"(d[2]), "+f"(d[3])
        : "r"(a0), "r"(a1), "r"(a2), "r"(a3), "r"(b0), "r"(b1));
}

// rotated-chunk address for 256B rows
__device__ __forceinline__ int radr(int row, int chunk) {
    return row * 256 + (((chunk) + row) & 15) * 16;
}

// ---------------------------------------------------------------------------
// Kernel A: e_ = Wd^T e + b -> bf16 hi/lo, both layouts, coalesced stores.
// grid (4 c-quarters, B), 512 threads.
// ---------------------------------------------------------------------------
__global__ __launch_bounds__(512) void ker_e(const float* __restrict__ e,
                                             const float* __restrict__ Wd,
                                             const float* __restrict__ bias) {
    __shared__ float es[DEn * Tn];    // [d][t] 32KB
    __shared__ uint32_t pk[32 * 33];  // [c_local][t] hi|lo<<16, padded
    int cq = blockIdx.x, b = blockIdx.y;
    int tid = threadIdx.x;
    int c = tid & 31, tp = tid >> 5;  // c local, t-pair 0..15

    const float* eb = e + (size_t)b * DEn * Tn;
    for (int i = tid; i < DEn * Tn; i += 512) es[i] = eb[i];
    __syncthreads();

    int cg = cq * 32 + c;
    float bv = bias[cg];
    float a0 = bv, a1 = bv;
#pragma unroll 8
    for (int d = 0; d < DEn; d++) {
        float w = Wd[d * Cn + cg];
        a0 = fmaf(w, es[d * Tn + 2 * tp], a0);
        a1 = fmaf(w, es[d * Tn + 2 * tp + 1], a1);
    }
    unsigned short h0, l0, h1, l1;
    bsplit(a0, h0, l0);
    bsplit(a1, h1, l1);
    pk[c * 33 + 2 * tp] = (uint32_t)h0 | ((uint32_t)l0 << 16);
    pk[c * 33 + 2 * tp + 1] = (uint32_t)h1 | ((uint32_t)l1 << 16);
    __syncthreads();

    // et arrays: [t][c] rows, u32 = c-pair
    {
        int t = tid >> 4, cp = tid & 15;
        uint32_t v0 = pk[(2 * cp) * 33 + t], v1 = pk[(2 * cp + 1) * 33 + t];
        uint32_t hi = (v0 & 0xFFFFu) | ((v1 & 0xFFFFu) << 16);
        uint32_t lo = (v0 >> 16) | ((v1 >> 16) << 16);
        size_t base = (size_t)b * Tn * Cn + t * Cn + cq * 32;
        ((uint32_t*)(g_et_hi + base))[cp] = hi;
        ((uint32_t*)(g_et_lo + base))[cp] = lo;
    }
    // ec arrays: [c][t] rows, u32 = t-pair
    {
        int cL = tid >> 4, tp2 = tid & 15;
        uint32_t v0 = pk[cL * 33 + 2 * tp2], v1 = pk[cL * 33 + 2 * tp2 + 1];
        uint32_t hi = (v0 & 0xFFFFu) | ((v1 & 0xFFFFu) << 16);
        uint32_t lo = (v0 >> 16) | ((v1 >> 16) << 16);
        size_t base = (size_t)b * Cn * Tn + (size_t)(cq * 32 + cL) * Tn;
        ((uint32_t*)(g_ec_hi + base))[tp2] = hi;
        ((uint32_t*)(g_ec_lo + base))[tp2] = lo;
    }
}

// ---------------------------------------------------------------------------
// Kernel B: warp-specialized mma.sync attention tile. 512 thr, 2 CTAs/SM.
//   warps 0-7  (compute): GEMM1 (A from gmem, B=et smem), softmax, ABUF, GEMM2
//   warps 8-15 (copy): stage et/ec, h->out passthrough, GEMM2 (beta via ABUF)
// ---------------------------------------------------------------------------
__global__ __launch_bounds__(512, 2) void ker_attn(const float* __restrict__ h,
                                                   float* __restrict__ out) {
    extern __shared__ char sm[];
    int tid = threadIdx.x;
    int lane = tid & 31, wid = tid >> 5;
    int g = lane >> 2, tig = lane & 3;
    int tile = blockIdx.x, b = blockIdx.y;
    size_t row0 = (size_t)b * HWn + (size_t)tile * NT;

    float2 buf[4];
    const float* hrow0 = 0;
    const float* hrow8 = 0;

    if (wid >= 8) {
        // ---- copy warps: stage et + ec into smem ----
        int ct = tid - 256;
        const uint4* eth = (const uint4*)(g_et_hi + (size_t)b * Tn * Cn);
        const uint4* etl = (const uint4*)(g_et_lo + (size_t)b * Tn * Cn);
#pragma unroll
        for (int it = 0; it < 2; it++) {
            int idx = it * 256 + ct;
            int t = idx >> 4, ch = idx & 15;
            int dst = radr(t, ch);
            *(uint4*)(sm + SM_ET_HI + dst) = eth[idx];
            *(uint4*)(sm + SM_ET_LO + dst) = etl[idx];
        }
        const uint4* ech = (const uint4*)(g_ec_hi + (size_t)b * Cn * Tn);
        const uint4* ecl = (const uint4*)(g_ec_lo + (size_t)b * Cn * Tn);
#pragma unroll
        for (int it = 0; it < 2; it++) {
            int idx = it * 256 + ct;
            int c = idx >> 2, ch = idx & 3;
            int dst = c * 80 + ch * 16;
            *(uint4*)(sm + SM_EC_HI + dst) = ech[idx];
            *(uint4*)(sm + SM_EC_LO + dst) = ecl[idx];
        }
    } else {
        // ---- compute warps: prefetch A kstep 0 from gmem ----
        int rA = wid * 16 + g;
        hrow0 = h + (row0 + rA) * Cn;
        hrow8 = h + (row0 + rA + 8) * Cn;
        buf[0] = *(const float2*)(hrow0 + 2 * tig);
        buf[1] = *(const float2*)(hrow0 + 8 + 2 * tig);
        buf[2] = *(const float2*)(hrow8 + 2 * tig);
        buf[3] = *(const float2*)(hrow8 + 8 + 2 * tig);
    }
    __syncthreads();  // (1) et/ec staged

    uint32_t af[16];  // beta A-fragments: [ks2][0..3 hi, 4..7 lo]

    if (wid < 8) {
        // ---- GEMM1: D1[n][t] = sum_c h.et, 3-product bf16 split ----
        float d[4][4];
#pragma unroll
        for (int i = 0; i < 4; i++)
#pragma unroll
            for (int j = 0; j < 4; j++) d[i][j] = 0.f;

#pragma unroll
        for (int ks = 0; ks < 8; ks++) {
            float2 cur[4];
#pragma unroll
            for (int i = 0; i < 4; i++) cur[i] = buf[i];
            if (ks < 7) {
                int cc = 16 * (ks + 1) + 2 * tig;
                buf[0] = *(const float2*)(hrow0 + cc);
                buf[1] = *(const float2*)(hrow0 + 8 + cc);
                buf[2] = *(const float2*)(hrow8 + cc);
                buf[3] = *(const float2*)(hrow8 + 8 + cc);
            }
            uint32_t ahi[4], alo[4];
            bsplit2(cur[0], ahi[0], alo[0]);  // row g,  k-low
            bsplit2(cur[2], ahi[1], alo[1]);  // row g+8, k-low
            bsplit2(cur[1], ahi[2], alo[2]);  // row g,  k-high
            bsplit2(cur[3], ahi[3], alo[3]);  // row g+8, k-high
            int c0 = 2 * ks, c1 = 2 * ks + 1, o = 4 * tig;
#pragma unroll
            for (int tt = 0; tt < 4; tt++) {
                int tB = tt * 8 + g;
                uint32_t bh0 = *(const uint32_t*)(sm + SM_ET_HI + radr(tB, c0) + o);
                uint32_t bh1 = *(const uint32_t*)(sm + SM_ET_HI + radr(tB, c1) + o);
                uint32_t bl0 = *(const uint32_t*)(sm + SM_ET_LO + radr(tB, c0) + o);
                uint32_t bl1 = *(const uint32_t*)(sm + SM_ET_LO + radr(tB, c1) + o);
                mma16816(d[tt], ahi[0], ahi[1], ahi[2], ahi[3], bh0, bh1);
                mma16816(d[tt], ahi[0], ahi[1], ahi[2], ahi[3], bl0, bl1);
                mma16816(d[tt], alo[0], alo[1], alo[2], alo[3], bh0, bh1);
            }
        }

        // ---- softmax over t, fully warp-local ----
        // row g: d[tt][0],d[tt][1] (t = 8tt+2tig+{0,1}); row g+8: d[tt][2],d[tt][3]
        float mA = -1e30f, mB = -1e30f;
#pragma unroll
        for (int tt = 0; tt < 4; tt++) {
            mA = fmaxf(mA, fmaxf(d[tt][0], d[tt][1]));
            mB = fmaxf(mB, fmaxf(d[tt][2], d[tt][3]));
        }
#pragma unroll
        for (int o = 1; o <= 2; o <<= 1) {
            mA = fmaxf(mA, __shfl_xor_sync(0xffffffffu, mA, o));
            mB = fmaxf(mB, __shfl_xor_sync(0xffffffffu, mB, o));
        }
        float sA = 0.f, sB = 0.f;
#pragma unroll
        for (int tt = 0; tt < 4; tt++) {
            d[tt][0] = __expf(d[tt][0] - mA);
            d[tt][1] = __expf(d[tt][1] - mA);
            d[tt][2] = __expf(d[tt][2] - mB);
            d[tt][3] = __expf(d[tt][3] - mB);
            sA += d[tt][0] + d[tt][1];
            sB += d[tt][2] + d[tt][3];
        }
#pragma unroll
        for (int o = 1; o <= 2; o <<= 1) {
            sA += __shfl_xor_sync(0xffffffffu, sA, o);
            sB += __shfl_xor_sync(0xffffffffu, sB, o);
        }
        float invA = __fdividef(1.0f, sA);
        float invB = __fdividef(1.0f, sB);

        // ---- pack beta A-fragments for both GEMM2 ksteps ----
#pragma unroll
        for (int ks2 = 0; ks2 < 2; ks2++) {
            unsigned short x0, y0, x1, y1;
            // a0: row g, t=16ks2+2tig,+1 -> d[2ks2][0..1]
            bsplit(d[2 * ks2][0] * invA, x0, y0);
            bsplit(d[2 * ks2][1] * invA, x1, y1);
            af[ks2 * 8 + 0] = pkk(x0, x1);
            af[ks2 * 8 + 4] = pkk(y0, y1);
            // a1: row g+8 -> d[2ks2][2..3]
            bsplit(d[2 * ks2][2] * invB, x0, y0);
            bsplit(d[2 * ks2][3] * invB, x1, y1);
            af[ks2 * 8 + 1] = pkk(x0, x1);
            af[ks2 * 8 + 5] = pkk(y0, y1);
            // a2: row g, t=16ks2+8+2tig -> d[2ks2+1][0..1]
            bsplit(d[2 * ks2 + 1][0] * invA, x0, y0);
            bsplit(d[2 * ks2 + 1][1] * invA, x1, y1);
            af[ks2 * 8 + 2] = pkk(x0, x1);
            af[ks2 * 8 + 6] = pkk(y0, y1);
            // a3: row g+8 -> d[2ks2+1][2..3]
            bsplit(d[2 * ks2 + 1][2] * invB, x0, y0);
            bsplit(d[2 * ks2 + 1][3] * invB, x1, y1);
            af[ks2 * 8 + 3] = pkk(x0, x1);
            af[ks2 * 8 + 7] = pkk(y0, y1);
        }
        // publish to ABUF for the copy-warp twin
#pragma unroll
        for (int r = 0; r < 16; r++)
            *(uint32_t*)(sm + SM_ABUF + ((wid * 16 + r) * 32 + lane) * 4) = af[r];
    } else {
        // ---- copy warps: h -> out passthrough (runs during GEMM1) ----
        const float4* hg = (const float4*)(h + row0 * Cn);
        float4* outg = (float4*)out;
        int ct = tid - 256;
#pragma unroll
        for (int it = 0; it < 16; it++) {
            int idx = it * 256 + ct;
            int n = idx >> 5, q = idx & 31;
            outg[(row0 + n) * 64 + 32 + q] = hg[idx];
        }
    }
    __syncthreads();  // (2) ABUF ready

    if (wid >= 8) {
#pragma unroll
        for (int r = 0; r < 16; r++)
            af[r] = *(const uint32_t*)(sm + SM_ABUF +
                                       (((wid - 8) * 16 + r) * 32 + lane) * 4);
    }

    // ---- GEMM2: D2[n][c] = sum_t beta.ec, 3-product split ----
    int mt = wid & 7, th = wid >> 3;
    int n0 = mt * 16 + g;
#pragma unroll
    for (int pass = 0; pass < 2; pass++) {
        float d2[4][4];
#pragma unroll
        for (int i = 0; i < 4; i++)
#pragma unroll
            for (int j = 0; j < 4; j++) d2[i][j] = 0.f;
#pragma unroll
        for (int ks2 = 0; ks2 < 2; ks2++) {
            const uint32_t* a = af + ks2 * 8;
#pragma unroll
            for (int tl = 0; tl < 4; tl++) {
                int crow = th * 64 + pass * 32 + tl * 8 + g;
                int ob = crow * 80 + 32 * ks2 + 4 * tig;
                uint32_t b0h = *(const uint32_t*)(sm + SM_EC_HI + ob);
                uint32_t b1h = *(const uint32_t*)(sm + SM_EC_HI + ob + 16);
                uint32_t b0l = *(const uint32_t*)(sm + SM_EC_LO + ob);
                uint32_t b1l = *(const uint32_t*)(sm + SM_EC_LO + ob + 16);
                mma16816(d2[tl], a[0], a[1], a[2], a[3], b0h, b1h);
                mma16816(d2[tl], a[0], a[1], a[2], a[3], b0l, b1l);
                mma16816(d2[tl], a[4], a[5], a[6], a[7], b0h, b1h);
            }
        }
#pragma unroll
        for (int tl = 0; tl < 4; tl++) {
            int col = th * 64 + pass * 32 + tl * 8 + 2 * tig;
            *(float2*)(out + (row0 + n0) * 256 + col) =
                make_float2(d2[tl][0], d2[tl][1]);
            *(float2*)(out + (row0 + n0 + 8) * 256 + col) =
                make_float2(d2[tl][2], d2[tl][3]);
        }
    }
}

// ---------------------------------------------------------------------------
extern "C" void kernel_launch(void* const* d_in, const int* in_sizes, int n_in,
                              void* d_out, int out_size) {
    const float* e    = (const float*)d_in[0];  // [B, DE, T]
    const float* h    = (const float*)d_in[1];  // [B, H, W, C]
    const float* Wd   = (const float*)d_in[2];  // [DE, C]
    const float* bias = (const float*)d_in[3];  // [C]
    float* out = (float*)d_out;                 // [B, H, W, 2C]

    (void)in_sizes; (void)n_in; (void)out_size;

    cudaFuncSetAttribute(ker_attn, cudaFuncAttributeMaxDynamicSharedMemorySize,
                         SMEM_BYTES);

    ker_e<<<dim3(4, Bn), 512>>>(e, Wd, bias);
    ker_attn<<<dim3(NTILES, Bn), 512, SMEM_BYTES>>>(h, out);
}

// round 9
// speedup vs baseline: 3.4573x; 1.0951x over previous
#include <cuda_runtime.h>
#include <cuda_bf16.h>
#include <cstdint>

#define Bn 32
#define DEn 256
#define Tn 32
#define Cn 128
#define HWn 16384
#define NT 128
#define NTILES (HWn / NT)

// bf16 hi/lo splits of the projection, both layouts
__device__ __align__(16) unsigned short g_et_hi[Bn * Tn * Cn];  // [b][t][c]
__device__ __align__(16) unsigned short g_et_lo[Bn * Tn * Cn];
__device__ __align__(16) unsigned short g_ec_hi[Bn * Cn * Tn];  // [b][c][t]
__device__ __align__(16) unsigned short g_ec_lo[Bn * Cn * Tn];

// ker_attn smem byte offsets (36.9KB total -> 4 CTAs/SM)
#define SM_ET_HI 0        // 32 rows x 256B rotated
#define SM_ET_LO 8192
#define SM_EC_HI 16384    // 128 rows x 80B
#define SM_EC_LO 26624
#define SMEM_BYTES 36864

__device__ __forceinline__ void bsplit(float x, unsigned short& h,
                                       unsigned short& l) {
    __nv_bfloat16 hb = __float2bfloat16_rn(x);
    float hf = __bfloat162float(hb);
    __nv_bfloat16 lb = __float2bfloat16_rn(x - hf);
    h = *(unsigned short*)&hb;
    l = *(unsigned short*)&lb;
}
__device__ __forceinline__ uint32_t pkk(unsigned short lo, unsigned short hi) {
    return (uint32_t)lo | ((uint32_t)hi << 16);
}
__device__ __forceinline__ void bsplit2(float2 v, uint32_t& hw, uint32_t& lw) {
    unsigned short h0, l0, h1, l1;
    bsplit(v.x, h0, l0);
    bsplit(v.y, h1, l1);
    hw = pkk(h0, h1);
    lw = pkk(l0, l1);
}

__device__ __forceinline__ void mma16816(float d[4], uint32_t a0, uint32_t a1,
                                         uint32_t a2, uint32_t a3, uint32_t b0,
                                         uint32_t b1) {
    asm volatile(
        "mma.sync.aligned.m16n8k16.row.col.f32.bf16.bf16.f32 "
        "{%0,%1,%2,%3},{%4,%5,%6,%7},{%8,%9},{%0,%1,%2,%3};"
        : "+f"(d[0]), "+f"(d[1]), "+f"(d[2]), "+f"(d[3])
        : "r"(a0), "r"(a1), "r"(a2), "r"(a3), "r"(b0), "r"(b1));
}

// rotated-chunk address for 256B rows
__device__ __forceinline__ int radr(int row, int chunk) {
    return row * 256 + (((chunk) + row) & 15) * 16;
}

// ---------------------------------------------------------------------------
// Kernel A: e_ = Wd^T e + b -> bf16 hi/lo, both layouts. All-smem inner loop.
// grid (4 c-quarters, B), 512 threads. dyn smem: es 32KB | wds 32KB | pk 4.2KB
// ---------------------------------------------------------------------------
__global__ __launch_bounds__(512) void ker_e(const float* __restrict__ e,
                                             const float* __restrict__ Wd,
                                             const float* __restrict__ bias) {
    extern __shared__ float dsm[];
    float* es = dsm;                       // [d][t] 256x32
    float* wds = dsm + 8192;               // [d][c_local] 256x32
    uint32_t* pk = (uint32_t*)(dsm + 16384);  // [32][33] hi|lo<<16

    int cq = blockIdx.x, b = blockIdx.y;
    int tid = threadIdx.x;
    int c = tid & 31, tp = tid >> 5;  // c local, t-pair 0..15

    const float* eb = e + (size_t)b * DEn * Tn;
    for (int i = tid; i < DEn * Tn; i += 512) {
        es[i] = eb[i];
        int d = i >> 5, cl = i & 31;
        wds[i] = Wd[d * Cn + cq * 32 + cl];
    }
    __syncthreads();

    float bv = bias[cq * 32 + c];
    float a0 = bv, a1 = bv;
#pragma unroll 8
    for (int d = 0; d < DEn; d++) {
        float w = wds[d * 32 + c];
        a0 = fmaf(w, es[d * Tn + 2 * tp], a0);
        a1 = fmaf(w, es[d * Tn + 2 * tp + 1], a1);
    }
    unsigned short h0, l0, h1, l1;
    bsplit(a0, h0, l0);
    bsplit(a1, h1, l1);
    pk[c * 33 + 2 * tp] = (uint32_t)h0 | ((uint32_t)l0 << 16);
    pk[c * 33 + 2 * tp + 1] = (uint32_t)h1 | ((uint32_t)l1 << 16);
    __syncthreads();

    // et arrays: [t][c] rows, u32 = c-pair
    {
        int t = tid >> 4, cp = tid & 15;
        uint32_t v0 = pk[(2 * cp) * 33 + t], v1 = pk[(2 * cp + 1) * 33 + t];
        uint32_t hi = (v0 & 0xFFFFu) | ((v1 & 0xFFFFu) << 16);
        uint32_t lo = (v0 >> 16) | ((v1 >> 16) << 16);
        size_t base = (size_t)b * Tn * Cn + t * Cn + cq * 32;
        ((uint32_t*)(g_et_hi + base))[cp] = hi;
        ((uint32_t*)(g_et_lo + base))[cp] = lo;
    }
    // ec arrays: [c][t] rows, u32 = t-pair
    {
        int cL = tid >> 4, tp2 = tid & 15;
        uint32_t v0 = pk[cL * 33 + 2 * tp2], v1 = pk[cL * 33 + 2 * tp2 + 1];
        uint32_t hi = (v0 & 0xFFFFu) | ((v1 & 0xFFFFu) << 16);
        uint32_t lo = (v0 >> 16) | ((v1 >> 16) << 16);
        size_t base = (size_t)b * Cn * Tn + (size_t)(cq * 32 + cL) * Tn;
        ((uint32_t*)(g_ec_hi + base))[tp2] = hi;
        ((uint32_t*)(g_ec_lo + base))[tp2] = lo;
    }
}

// ---------------------------------------------------------------------------
// Kernel B: uniform-warp mma.sync attention tile. 256 thr, 4 CTAs/SM.
// Each warp owns 16 rows end-to-end: GEMM1 (A from gmem + fused h->out store),
// warp-local softmax (beta stays in registers), GEMM2 over all 128 cols.
// ---------------------------------------------------------------------------
__global__ __launch_bounds__(256, 4) void ker_attn(const float* __restrict__ h,
                                                   float* __restrict__ out) {
    extern __shared__ char sm[];
    int tid = threadIdx.x;
    int lane = tid & 31, wid = tid >> 5;
    int g = lane >> 2, tig = lane & 3;
    int tile = blockIdx.x, b = blockIdx.y;
    size_t row0 = (size_t)b * HWn + (size_t)tile * NT;

    // ---- stage et + ec (all warps) ----
    {
        const uint4* eth = (const uint4*)(g_et_hi + (size_t)b * Tn * Cn);
        const uint4* etl = (const uint4*)(g_et_lo + (size_t)b * Tn * Cn);
#pragma unroll
        for (int it = 0; it < 2; it++) {
            int idx = it * 256 + tid;
            int t = idx >> 4, ch = idx & 15;
            int dst = radr(t, ch);
            *(uint4*)(sm + SM_ET_HI + dst) = eth[idx];
            *(uint4*)(sm + SM_ET_LO + dst) = etl[idx];
        }
        const uint4* ech = (const uint4*)(g_ec_hi + (size_t)b * Cn * Tn);
        const uint4* ecl = (const uint4*)(g_ec_lo + (size_t)b * Cn * Tn);
#pragma unroll
        for (int it = 0; it < 2; it++) {
            int idx = it * 256 + tid;
            int c = idx >> 2, ch = idx & 3;
            int dst = c * 80 + ch * 16;
            *(uint4*)(sm + SM_EC_HI + dst) = ech[idx];
            *(uint4*)(sm + SM_EC_LO + dst) = ecl[idx];
        }
    }

    // ---- prefetch A kstep 0 (h rows of this warp's slab) ----
    int rA = wid * 16 + g;
    const float* hrow0 = h + (row0 + rA) * Cn;              // row rA
    float* orow0 = out + (row0 + rA) * 256 + 128;           // passthrough dst
    float2 buf[4];
    buf[0] = *(const float2*)(hrow0 + 2 * tig);
    buf[1] = *(const float2*)(hrow0 + 8 + 2 * tig);
    buf[2] = *(const float2*)(hrow0 + 1024 + 2 * tig);      // row rA+8
    buf[3] = *(const float2*)(hrow0 + 1024 + 8 + 2 * tig);
    __syncthreads();  // et/ec staged

    // ---- GEMM1: D1[n][t] = sum_c h.et, 3-product bf16 split,
    //      with fused h->out passthrough store ----
    float d[4][4];
#pragma unroll
    for (int i = 0; i < 4; i++)
#pragma unroll
        for (int j = 0; j < 4; j++) d[i][j] = 0.f;

#pragma unroll
    for (int ks = 0; ks < 8; ks++) {
        uint32_t ahi[4], alo[4];
        bsplit2(buf[0], ahi[0], alo[0]);  // row g,   k-low
        bsplit2(buf[2], ahi[1], alo[1]);  // row g+8, k-low
        bsplit2(buf[1], ahi[2], alo[2]);  // row g,   k-high
        bsplit2(buf[3], ahi[3], alo[3]);  // row g+8, k-high
        // fused passthrough: store exactly what we loaded
        int cc = 16 * ks + 2 * tig;
        *(float2*)(orow0 + cc) = buf[0];
        *(float2*)(orow0 + cc + 8) = buf[1];
        *(float2*)(orow0 + 2048 + cc) = buf[2];
        *(float2*)(orow0 + 2048 + cc + 8) = buf[3];
        if (ks < 7) {
            int nc = 16 * (ks + 1) + 2 * tig;
            buf[0] = *(const float2*)(hrow0 + nc);
            buf[1] = *(const float2*)(hrow0 + 8 + nc);
            buf[2] = *(const float2*)(hrow0 + 1024 + nc);
            buf[3] = *(const float2*)(hrow0 + 1024 + 8 + nc);
        }
        int c0 = 2 * ks, c1 = 2 * ks + 1, o = 4 * tig;
#pragma unroll
        for (int tt = 0; tt < 4; tt++) {
            int tB = tt * 8 + g;
            uint32_t bh0 = *(const uint32_t*)(sm + SM_ET_HI + radr(tB, c0) + o);
            uint32_t bh1 = *(const uint32_t*)(sm + SM_ET_HI + radr(tB, c1) + o);
            uint32_t bl0 = *(const uint32_t*)(sm + SM_ET_LO + radr(tB, c0) + o);
            uint32_t bl1 = *(const uint32_t*)(sm + SM_ET_LO + radr(tB, c1) + o);
            mma16816(d[tt], ahi[0], ahi[1], ahi[2], ahi[3], bh0, bh1);
            mma16816(d[tt], ahi[0], ahi[1], ahi[2], ahi[3], bl0, bl1);
            mma16816(d[tt], alo[0], alo[1], alo[2], alo[3], bh0, bh1);
        }
    }

    // ---- softmax over t, fully warp-local ----
    float mA = -1e30f, mB = -1e30f;
#pragma unroll
    for (int tt = 0; tt < 4; tt++) {
        mA = fmaxf(mA, fmaxf(d[tt][0], d[tt][1]));
        mB = fmaxf(mB, fmaxf(d[tt][2], d[tt][3]));
    }
#pragma unroll
    for (int o = 1; o <= 2; o <<= 1) {
        mA = fmaxf(mA, __shfl_xor_sync(0xffffffffu, mA, o));
        mB = fmaxf(mB, __shfl_xor_sync(0xffffffffu, mB, o));
    }
    float sA = 0.f, sB = 0.f;
#pragma unroll
    for (int tt = 0; tt < 4; tt++) {
        d[tt][0] = __expf(d[tt][0] - mA);
        d[tt][1] = __expf(d[tt][1] - mA);
        d[tt][2] = __expf(d[tt][2] - mB);
        d[tt][3] = __expf(d[tt][3] - mB);
        sA += d[tt][0] + d[tt][1];
        sB += d[tt][2] + d[tt][3];
    }
#pragma unroll
    for (int o = 1; o <= 2; o <<= 1) {
        sA += __shfl_xor_sync(0xffffffffu, sA, o);
        sB += __shfl_xor_sync(0xffffffffu, sB, o);
    }
    float invA = __fdividef(1.0f, sA);
    float invB = __fdividef(1.0f, sB);

    // ---- pack beta A-fragments for both GEMM2 ksteps (register-only) ----
    uint32_t af[16];  // [ks2][0..3 hi, 4..7 lo]
#pragma unroll
    for (int ks2 = 0; ks2 < 2; ks2++) {
        unsigned short x0, y0, x1, y1;
        bsplit(d[2 * ks2][0] * invA, x0, y0);
        bsplit(d[2 * ks2][1] * invA, x1, y1);
        af[ks2 * 8 + 0] = pkk(x0, x1);
        af[ks2 * 8 + 4] = pkk(y0, y1);
        bsplit(d[2 * ks2][2] * invB, x0, y0);
        bsplit(d[2 * ks2][3] * invB, x1, y1);
        af[ks2 * 8 + 1] = pkk(x0, x1);
        af[ks2 * 8 + 5] = pkk(y0, y1);
        bsplit(d[2 * ks2 + 1][0] * invA, x0, y0);
        bsplit(d[2 * ks2 + 1][1] * invA, x1, y1);
        af[ks2 * 8 + 2] = pkk(x0, x1);
        af[ks2 * 8 + 6] = pkk(y0, y1);
        bsplit(d[2 * ks2 + 1][2] * invB, x0, y0);
        bsplit(d[2 * ks2 + 1][3] * invB, x1, y1);
        af[ks2 * 8 + 3] = pkk(x0, x1);
        af[ks2 * 8 + 7] = pkk(y0, y1);
    }

    // ---- GEMM2: D2[n][c] = sum_t beta.ec, 3-product split; all 128 cols ----
    int n0 = wid * 16 + g;
#pragma unroll
    for (int pass = 0; pass < 4; pass++) {
        float d2[4][4];
#pragma unroll
        for (int i = 0; i < 4; i++)
#pragma unroll
            for (int j = 0; j < 4; j++) d2[i][j] = 0.f;
#pragma unroll
        for (int ks2 = 0; ks2 < 2; ks2++) {
            const uint32_t* a = af + ks2 * 8;
#pragma unroll
            for (int tl = 0; tl < 4; tl++) {
                int crow = pass * 32 + tl * 8 + g;
                int ob = crow * 80 + 32 * ks2 + 4 * tig;
                uint32_t b0h = *(const uint32_t*)(sm + SM_EC_HI + ob);
                uint32_t b1h = *(const uint32_t*)(sm + SM_EC_HI + ob + 16);
                uint32_t b0l = *(const uint32_t*)(sm + SM_EC_LO + ob);
                uint32_t b1l = *(const uint32_t*)(sm + SM_EC_LO + ob + 16);
                mma16816(d2[tl], a[0], a[1], a[2], a[3], b0h, b1h);
                mma16816(d2[tl], a[0], a[1], a[2], a[3], b0l, b1l);
                mma16816(d2[tl], a[4], a[5], a[6], a[7], b0h, b1h);
            }
        }
#pragma unroll
        for (int tl = 0; tl < 4; tl++) {
            int col = pass * 32 + tl * 8 + 2 * tig;
            *(float2*)(out + (row0 + n0) * 256 + col) =
                make_float2(d2[tl][0], d2[tl][1]);
            *(float2*)(out + (row0 + n0 + 8) * 256 + col) =
                make_float2(d2[tl][2], d2[tl][3]);
        }
    }
}

// ---------------------------------------------------------------------------
extern "C" void kernel_launch(void* const* d_in, const int* in_sizes, int n_in,
                              void* d_out, int out_size) {
    const float* e    = (const float*)d_in[0];  // [B, DE, T]
    const float* h    = (const float*)d_in[1];  // [B, H, W, C]
    const float* Wd   = (const float*)d_in[2];  // [DE, C]
    const float* bias = (const float*)d_in[3];  // [C]
    float* out = (float*)d_out;                 // [B, H, W, 2C]

    (void)in_sizes; (void)n_in; (void)out_size;

    cudaFuncSetAttribute(ker_e, cudaFuncAttributeMaxDynamicSharedMemorySize,
                         70016);
    cudaFuncSetAttribute(ker_attn, cudaFuncAttributeMaxDynamicSharedMemorySize,
                         SMEM_BYTES);

    ker_e<<<dim3(4, Bn), 512, 70016>>>(e, Wd, bias);
    ker_attn<<<dim3(NTILES, Bn), 256, SMEM_BYTES>>>(h, out);
}